// round 9
// baseline (speedup 1.0000x reference)
#include <cuda_runtime.h>
#include <math.h>

#define NN 100000
#define EE 1600000
#define BB 64
#define DIN 9
#define HD 128
#define KK 256
#define SLOTS 96
#define LN_EPS 1e-5f

// ---------------- scratch ----------------
__device__ float g_h0[NN * HD];
__device__ float g_h1[NN * HD];
__device__ float g_agg[NN * HD];
__device__ float g_wT[3 * KK * HD];   // per layer: [k][c]; k<128 = Wl^T, k>=128 = Wr^T
__device__ int   g_deg[NN];
__device__ int   g_slots[NN * SLOTS];
__device__ float g_psum[BB * HD];
__device__ unsigned g_pmax[BB * HD];
__device__ int   g_pcnt[BB];

// ---------------- launch 1: init (zero deg/pool) + weight transpose ----------------
__global__ void init_kernel(const float* __restrict__ Wl1, const float* __restrict__ Wr1,
                            const float* __restrict__ Wl2, const float* __restrict__ Wr2,
                            const float* __restrict__ Wl3, const float* __restrict__ Wr3) {
    int i = blockIdx.x * blockDim.x + threadIdx.x;
    if (i < NN) g_deg[i] = 0;
    if (i < BB * HD) { g_psum[i] = 0.0f; g_pmax[i] = 0u; }
    if (i < BB) g_pcnt[i] = 0;
    if (i < 3 * KK * HD) {
        int c = i & 127;
        int k = (i >> 7) & 255;
        int L = i >> 15;
        const float* W;
        int kk = k;
        if (k < HD) {
            W = (L == 0) ? Wl1 : (L == 1) ? Wl2 : Wl3;
        } else {
            W = (L == 0) ? Wr1 : (L == 1) ? Wr2 : Wr3;
            kk = k - HD;
        }
        g_wT[i] = W[c * HD + kk];
    }
}

// ---------------- launch 2: bucket build (deg count + slot scatter, no scan) ----------------
__global__ void build_kernel(const int* __restrict__ src, const int* __restrict__ dst) {
    int e = blockIdx.x * blockDim.x + threadIdx.x;
    if (e < EE) {
        int d = dst[e];
        int pos = atomicAdd(&g_deg[d], 1);
        if (pos < SLOTS) g_slots[d * SLOTS + pos] = src[e];
    }
}

// ---------------- launch 3: node embedder Linear(9->128) + LN + ReLU ----------------
#define ROWS_E 16
__global__ void embed_kernel(const float* __restrict__ x,
                             const float* __restrict__ W0,
                             const float* __restrict__ b0,
                             const float* __restrict__ g0,
                             const float* __restrict__ be0,
                             float* __restrict__ hout) {
    __shared__ float sx[DIN];
    __shared__ float red[8];
    int tid = threadIdx.x;
    float gc = g0[tid], bec = be0[tid], bc = b0[tid];
    float w[DIN];
#pragma unroll
    for (int k = 0; k < DIN; k++) w[k] = W0[tid * DIN + k];

    int row0 = blockIdx.x * ROWS_E;
    for (int r = 0; r < ROWS_E; r++) {
        int row = row0 + r;
        if (tid < DIN) sx[tid] = x[row * DIN + tid];
        __syncthreads();
        float acc = bc;
#pragma unroll
        for (int k = 0; k < DIN; k++) acc += w[k] * sx[k];
        float s1 = acc, s2 = acc * acc;
#pragma unroll
        for (int o = 16; o; o >>= 1) {
            s1 += __shfl_xor_sync(0xffffffffu, s1, o);
            s2 += __shfl_xor_sync(0xffffffffu, s2, o);
        }
        int wi = tid >> 5, l = tid & 31;
        if (l == 0) { red[wi] = s1; red[wi + 4] = s2; }
        __syncthreads();
        float t1 = red[0] + red[1] + red[2] + red[3];
        float t2 = red[4] + red[5] + red[6] + red[7];
        float mean = t1 * (1.0f / HD);
        float var = t2 * (1.0f / HD) - mean * mean;
        float rs = rsqrtf(var + LN_EPS);
        float v = (acc - mean) * rs * gc + bec;
        hout[row * HD + tid] = fmaxf(v, 0.0f);
        __syncthreads();
    }
}

// ---------------- mean aggregation: warp per node, lane-parallel slot fetch ----------------
__global__ void aggregate_kernel(const float* __restrict__ hin) {
    int warp = (blockIdx.x * blockDim.x + threadIdx.x) >> 5;
    int lane = threadIdx.x & 31;
    if (warp >= NN) return;
    int deg = g_deg[warp];
    const int* slots = g_slots + warp * SLOTS;
    float a0 = 0.f, a1 = 0.f, a2 = 0.f, a3 = 0.f;

    for (int base = 0; base < deg; base += 32) {
        int n = min(deg - base, 32);
        // one coalesced load fetches up to 32 neighbor indices
        int mysrc = (lane < n) ? __ldg(slots + base + lane) : 0;
        int j = 0;
        int nfull = n & ~3;
        for (; j < nfull; j += 4) {
            int s0 = __shfl_sync(0xffffffffu, mysrc, j + 0);
            int s1 = __shfl_sync(0xffffffffu, mysrc, j + 1);
            int s2 = __shfl_sync(0xffffffffu, mysrc, j + 2);
            int s3 = __shfl_sync(0xffffffffu, mysrc, j + 3);
            float4 v0 = __ldg((const float4*)(hin + (size_t)s0 * HD) + lane);
            float4 v1 = __ldg((const float4*)(hin + (size_t)s1 * HD) + lane);
            float4 v2 = __ldg((const float4*)(hin + (size_t)s2 * HD) + lane);
            float4 v3 = __ldg((const float4*)(hin + (size_t)s3 * HD) + lane);
            a0 += (v0.x + v1.x) + (v2.x + v3.x);
            a1 += (v0.y + v1.y) + (v2.y + v3.y);
            a2 += (v0.z + v1.z) + (v2.z + v3.z);
            a3 += (v0.w + v1.w) + (v2.w + v3.w);
        }
        for (; j < n; j++) {
            int s0 = __shfl_sync(0xffffffffu, mysrc, j);
            float4 v = __ldg((const float4*)(hin + (size_t)s0 * HD) + lane);
            a0 += v.x; a1 += v.y; a2 += v.z; a3 += v.w;
        }
    }
    float inv = 1.0f / (float)max(deg, 1);
    float4 out;
    out.x = a0 * inv; out.y = a1 * inv; out.z = a2 * inv; out.w = a3 * inv;
    *reinterpret_cast<float4*>(g_agg + (size_t)warp * HD + lane * 4) = out;
}

// ---------------- SAGE: 128x128xK=256 register-tiled GEMM + fused LN/ReLU ----------------
#define SBK 64
#define SAGE2_SMEM (SBK * HD * 4 + 128 * SBK * 4)   // 65536

__global__ __launch_bounds__(256, 2)
void sage2_kernel(const float* __restrict__ hin,
                  const float* __restrict__ wT,
                  const float* __restrict__ bl,
                  const float* __restrict__ gg,
                  const float* __restrict__ be,
                  float* __restrict__ hout) {
    extern __shared__ float sm[];
    float* w_s = sm;                 // [64][128]
    float* x_s = sm + SBK * HD;      // [128][64]

    int tid = threadIdx.x;
    int tx = tid & 31;
    int wy = tid >> 5;
    int row0 = blockIdx.x * 128;

    float acc[16][4];
#pragma unroll
    for (int r = 0; r < 16; r++) {
        acc[r][0] = 0.f; acc[r][1] = 0.f; acc[r][2] = 0.f; acc[r][3] = 0.f;
    }

    for (int ch = 0; ch < 4; ch++) {
        const float* xsrc = (ch < 2) ? g_agg : hin;
        int kofs = (ch & 1) * SBK;
        {
            int k4 = tid & 15, rr = tid >> 4;
#pragma unroll
            for (int it = 0; it < 8; it++) {
                int row = rr + it * 16;
                int grow = row0 + row;
                float4 v = make_float4(0.f, 0.f, 0.f, 0.f);
                if (grow < NN)
                    v = *(const float4*)(xsrc + (size_t)grow * HD + kofs + k4 * 4);
                ((float4*)(x_s + row * SBK))[k4] = v;
            }
        }
        {
            int c4 = tid & 31, kk = tid >> 5;
#pragma unroll
            for (int it = 0; it < 8; it++) {
                int k = kk + it * 8;
                ((float4*)(w_s + k * HD))[c4] =
                    *(const float4*)(wT + (size_t)(ch * SBK + k) * HD + c4 * 4);
            }
        }
        __syncthreads();

#pragma unroll 4
        for (int k4i = 0; k4i < SBK / 4; k4i++) {
            float4 b0 = ((float4*)(w_s + (4 * k4i + 0) * HD))[tx];
            float4 b1 = ((float4*)(w_s + (4 * k4i + 1) * HD))[tx];
            float4 b2 = ((float4*)(w_s + (4 * k4i + 2) * HD))[tx];
            float4 b3 = ((float4*)(w_s + (4 * k4i + 3) * HD))[tx];
#pragma unroll
            for (int r = 0; r < 16; r++) {
                float4 a = ((float4*)(x_s + (wy * 16 + r) * SBK))[k4i];  // broadcast
                acc[r][0] += a.x * b0.x + a.y * b1.x + a.z * b2.x + a.w * b3.x;
                acc[r][1] += a.x * b0.y + a.y * b1.y + a.z * b2.y + a.w * b3.y;
                acc[r][2] += a.x * b0.z + a.y * b1.z + a.z * b2.z + a.w * b3.z;
                acc[r][3] += a.x * b0.w + a.y * b1.w + a.z * b2.w + a.w * b3.w;
            }
        }
        __syncthreads();
    }

    float4 blv = *(const float4*)(bl + tx * 4);
    float4 gv  = *(const float4*)(gg + tx * 4);
    float4 bev = *(const float4*)(be + tx * 4);
#pragma unroll
    for (int r = 0; r < 16; r++) {
        float a0 = acc[r][0] + blv.x;
        float a1 = acc[r][1] + blv.y;
        float a2 = acc[r][2] + blv.z;
        float a3 = acc[r][3] + blv.w;
        float s1 = (a0 + a1) + (a2 + a3);
        float s2 = (a0 * a0 + a1 * a1) + (a2 * a2 + a3 * a3);
#pragma unroll
        for (int o = 16; o; o >>= 1) {
            s1 += __shfl_xor_sync(0xffffffffu, s1, o);
            s2 += __shfl_xor_sync(0xffffffffu, s2, o);
        }
        float mean = s1 * (1.0f / HD);
        float var  = s2 * (1.0f / HD) - mean * mean;
        float rs   = rsqrtf(var + LN_EPS);
        int row = row0 + wy * 16 + r;
        if (row < NN) {
            float4 o4;
            o4.x = fmaxf((a0 - mean) * rs * gv.x + bev.x, 0.f);
            o4.y = fmaxf((a1 - mean) * rs * gv.y + bev.y, 0.f);
            o4.z = fmaxf((a2 - mean) * rs * gv.z + bev.z, 0.f);
            o4.w = fmaxf((a3 - mean) * rs * gv.w + bev.w, 0.f);
            *(float4*)(hout + (size_t)row * HD + tx * 4) = o4;
        }
    }
}

// ---------------- pooling ----------------
#define POOL_CHUNK 256
__global__ void pool_kernel(const float* __restrict__ node,
                            const int* __restrict__ batch) {
    int n0 = blockIdx.x * POOL_CHUNK;
    int n1 = min(n0 + POOL_CHUNK, NN);
    int c = threadIdx.x;
    int cur = __ldg(&batch[n0]);
    float s = 0.0f, m = 0.0f;
    int cnt = 0;
    for (int i = n0; i < n1; i++) {
        int b = __ldg(&batch[i]);
        if (b != cur) {
            atomicAdd(&g_psum[cur * HD + c], s);
            atomicMax(&g_pmax[cur * HD + c], __float_as_uint(m));
            if (c == 0) atomicAdd(&g_pcnt[cur], cnt);
            cur = b; s = 0.0f; m = 0.0f; cnt = 0;
        }
        float v = node[(size_t)i * HD + c];
        s += v;
        m = fmaxf(m, v);
        cnt++;
    }
    atomicAdd(&g_psum[cur * HD + c], s);
    atomicMax(&g_pmax[cur * HD + c], __float_as_uint(m));
    if (c == 0) atomicAdd(&g_pcnt[cur], cnt);
}

__global__ void finalize_kernel(float* __restrict__ out) {
    int i = blockIdx.x * blockDim.x + threadIdx.x;
    if (i >= BB * HD) return;
    int b = i >> 7;
    int c = i & (HD - 1);
    float cnt = fmaxf((float)g_pcnt[b], 1.0f);
    out[(size_t)NN * HD + b * (2 * HD) + c] = g_psum[i] / cnt;
    out[(size_t)NN * HD + b * (2 * HD) + HD + c] = __uint_as_float(g_pmax[i]);
}

// ---------------- launch ----------------
extern "C" void kernel_launch(void* const* d_in, const int* in_sizes, int n_in,
                              void* d_out, int out_size) {
    const float* x   = (const float*)d_in[0];
    const int* eidx  = (const int*)d_in[1];
    const int* batch = (const int*)d_in[2];
    const float* W0 = (const float*)d_in[3];
    const float* b0 = (const float*)d_in[4];
    const float* g0 = (const float*)d_in[5];
    const float* be0 = (const float*)d_in[6];
    const float* Wl1 = (const float*)d_in[7];
    const float* bl1 = (const float*)d_in[8];
    const float* Wr1 = (const float*)d_in[9];
    const float* g1 = (const float*)d_in[10];
    const float* be1 = (const float*)d_in[11];
    const float* Wl2 = (const float*)d_in[12];
    const float* bl2 = (const float*)d_in[13];
    const float* Wr2 = (const float*)d_in[14];
    const float* g2 = (const float*)d_in[15];
    const float* be2 = (const float*)d_in[16];
    const float* Wl3 = (const float*)d_in[17];
    const float* bl3 = (const float*)d_in[18];
    const float* Wr3 = (const float*)d_in[19];
    const float* g3 = (const float*)d_in[20];
    const float* be3 = (const float*)d_in[21];
    float* out = (float*)d_out;

    const int* src = eidx;       // edge_index[0]
    const int* dst = eidx + EE;  // edge_index[1]

    static int attr_set = 0;
    if (!attr_set) {
        cudaFuncSetAttribute(sage2_kernel,
                             cudaFuncAttributeMaxDynamicSharedMemorySize, SAGE2_SMEM);
        attr_set = 1;
    }

    float* wT = 0;
    cudaGetSymbolAddress((void**)&wT, g_wT);

    int agg_blocks = (NN * 32 + 255) / 256;
    int sage_blocks = (NN + 127) / 128;

    // 1: init + weight transpose
    init_kernel<<<(NN + 255) / 256, 256>>>(Wl1, Wr1, Wl2, Wr2, Wl3, Wr3);
    // 2: bucket build
    build_kernel<<<(EE + 255) / 256, 256>>>(src, dst);
    // 3: embed
    embed_kernel<<<NN / ROWS_E, HD>>>(x, W0, b0, g0, be0, g_h0);
    // 4: aggregate (profiled slot)
    aggregate_kernel<<<agg_blocks, 256>>>(g_h0);
    sage2_kernel<<<sage_blocks, 256, SAGE2_SMEM>>>(g_h0, wT + 0 * KK * HD, bl1, g1, be1, g_h1);
    aggregate_kernel<<<agg_blocks, 256>>>(g_h1);
    sage2_kernel<<<sage_blocks, 256, SAGE2_SMEM>>>(g_h1, wT + 1 * KK * HD, bl2, g2, be2, g_h0);
    aggregate_kernel<<<agg_blocks, 256>>>(g_h0);
    sage2_kernel<<<sage_blocks, 256, SAGE2_SMEM>>>(g_h0, wT + 2 * KK * HD, bl3, g3, be3, out);

    // pooling
    pool_kernel<<<(NN + POOL_CHUNK - 1) / POOL_CHUNK, HD>>>(out, batch);
    finalize_kernel<<<(BB * HD + 255) / 256, 256>>>(out);
}

// round 10
// speedup vs baseline: 1.0066x; 1.0066x over previous
#include <cuda_runtime.h>
#include <math.h>

#define NN 100000
#define EE 1600000
#define BB 64
#define DIN 9
#define HD 128
#define KK 256
#define SLOTS 96
#define LN_EPS 1e-5f

// ---------------- scratch ----------------
__device__ float g_h0[NN * HD];
__device__ float g_h1[NN * HD];
__device__ float g_agg[NN * HD];
__device__ float g_wT[3 * KK * HD];   // per layer: [k][c]; k<128 = Wl^T, k>=128 = Wr^T
__device__ int   g_deg[NN];
__device__ int   g_slots[NN * SLOTS];
__device__ float g_psum[BB * HD];
__device__ unsigned g_pmax[BB * HD];
__device__ int   g_pcnt[BB];

// ---------------- launch 1: init (zero deg/pool) + weight transpose ----------------
__global__ void init_kernel(const float* __restrict__ Wl1, const float* __restrict__ Wr1,
                            const float* __restrict__ Wl2, const float* __restrict__ Wr2,
                            const float* __restrict__ Wl3, const float* __restrict__ Wr3) {
    int i = blockIdx.x * blockDim.x + threadIdx.x;
    if (i < NN) g_deg[i] = 0;
    if (i < BB * HD) { g_psum[i] = 0.0f; g_pmax[i] = 0u; }
    if (i < BB) g_pcnt[i] = 0;
    if (i < 3 * KK * HD) {
        int c = i & 127;
        int k = (i >> 7) & 255;
        int L = i >> 15;
        const float* W;
        int kk = k;
        if (k < HD) {
            W = (L == 0) ? Wl1 : (L == 1) ? Wl2 : Wl3;
        } else {
            W = (L == 0) ? Wr1 : (L == 1) ? Wr2 : Wr3;
            kk = k - HD;
        }
        g_wT[i] = W[c * HD + kk];
    }
}

// ---------------- launch 2: bucket build (deg count + slot scatter, no scan) ----------------
__global__ void build_kernel(const int* __restrict__ src, const int* __restrict__ dst) {
    int e = blockIdx.x * blockDim.x + threadIdx.x;
    if (e < EE) {
        int d = dst[e];
        int pos = atomicAdd(&g_deg[d], 1);
        if (pos < SLOTS) g_slots[d * SLOTS + pos] = src[e];
    }
}

// ---------------- launch 3: node embedder Linear(9->128) + LN + ReLU ----------------
#define ROWS_E 16
__global__ void embed_kernel(const float* __restrict__ x,
                             const float* __restrict__ W0,
                             const float* __restrict__ b0,
                             const float* __restrict__ g0,
                             const float* __restrict__ be0,
                             float* __restrict__ hout) {
    __shared__ float sx[DIN];
    __shared__ float red[8];
    int tid = threadIdx.x;
    float gc = g0[tid], bec = be0[tid], bc = b0[tid];
    float w[DIN];
#pragma unroll
    for (int k = 0; k < DIN; k++) w[k] = W0[tid * DIN + k];

    int row0 = blockIdx.x * ROWS_E;
    for (int r = 0; r < ROWS_E; r++) {
        int row = row0 + r;
        if (tid < DIN) sx[tid] = x[row * DIN + tid];
        __syncthreads();
        float acc = bc;
#pragma unroll
        for (int k = 0; k < DIN; k++) acc += w[k] * sx[k];
        float s1 = acc, s2 = acc * acc;
#pragma unroll
        for (int o = 16; o; o >>= 1) {
            s1 += __shfl_xor_sync(0xffffffffu, s1, o);
            s2 += __shfl_xor_sync(0xffffffffu, s2, o);
        }
        int wi = tid >> 5, l = tid & 31;
        if (l == 0) { red[wi] = s1; red[wi + 4] = s2; }
        __syncthreads();
        float t1 = red[0] + red[1] + red[2] + red[3];
        float t2 = red[4] + red[5] + red[6] + red[7];
        float mean = t1 * (1.0f / HD);
        float var = t2 * (1.0f / HD) - mean * mean;
        float rs = rsqrtf(var + LN_EPS);
        float v = (acc - mean) * rs * gc + bec;
        hout[row * HD + tid] = fmaxf(v, 0.0f);
        __syncthreads();
    }
}

// ---------------- mean aggregation v3: warp per node ----------------
// Broadcast index loads (all lanes load the same slot word -> 1 L1 wavefront,
// no cross-lane dependency) + 8 independent float4 gathers in flight (MLP=8).
// No launch_bounds reg cap so ptxas can keep all 8 gathers live.
__global__ void aggregate_kernel(const float* __restrict__ hin) {
    int node = (blockIdx.x * blockDim.x + threadIdx.x) >> 5;
    int lane = threadIdx.x & 31;
    if (node >= NN) return;
    int deg = g_deg[node];
    int n = min(deg, SLOTS);
    const int* sl = g_slots + node * SLOTS;

    float a0 = 0.f, a1 = 0.f, a2 = 0.f, a3 = 0.f;
    int j = 0;
    for (; j + 8 <= n; j += 8) {
        int i0 = sl[j + 0], i1 = sl[j + 1], i2 = sl[j + 2], i3 = sl[j + 3];
        int i4 = sl[j + 4], i5 = sl[j + 5], i6 = sl[j + 6], i7 = sl[j + 7];
        float4 v0 = *((const float4*)(hin + (size_t)i0 * HD) + lane);
        float4 v1 = *((const float4*)(hin + (size_t)i1 * HD) + lane);
        float4 v2 = *((const float4*)(hin + (size_t)i2 * HD) + lane);
        float4 v3 = *((const float4*)(hin + (size_t)i3 * HD) + lane);
        float4 v4 = *((const float4*)(hin + (size_t)i4 * HD) + lane);
        float4 v5 = *((const float4*)(hin + (size_t)i5 * HD) + lane);
        float4 v6 = *((const float4*)(hin + (size_t)i6 * HD) + lane);
        float4 v7 = *((const float4*)(hin + (size_t)i7 * HD) + lane);
        a0 += ((v0.x + v1.x) + (v2.x + v3.x)) + ((v4.x + v5.x) + (v6.x + v7.x));
        a1 += ((v0.y + v1.y) + (v2.y + v3.y)) + ((v4.y + v5.y) + (v6.y + v7.y));
        a2 += ((v0.z + v1.z) + (v2.z + v3.z)) + ((v4.z + v5.z) + (v6.z + v7.z));
        a3 += ((v0.w + v1.w) + (v2.w + v3.w)) + ((v4.w + v5.w) + (v6.w + v7.w));
    }
    for (; j + 2 <= n; j += 2) {
        int i0 = sl[j + 0], i1 = sl[j + 1];
        float4 v0 = *((const float4*)(hin + (size_t)i0 * HD) + lane);
        float4 v1 = *((const float4*)(hin + (size_t)i1 * HD) + lane);
        a0 += v0.x + v1.x; a1 += v0.y + v1.y;
        a2 += v0.z + v1.z; a3 += v0.w + v1.w;
    }
    if (j < n) {
        int i0 = sl[j];
        float4 v = *((const float4*)(hin + (size_t)i0 * HD) + lane);
        a0 += v.x; a1 += v.y; a2 += v.z; a3 += v.w;
    }
    float inv = 1.0f / (float)max(deg, 1);
    float4 out;
    out.x = a0 * inv; out.y = a1 * inv; out.z = a2 * inv; out.w = a3 * inv;
    *reinterpret_cast<float4*>(g_agg + (size_t)node * HD + lane * 4) = out;
}

// ---------------- SAGE: 128x128xK=256 register-tiled GEMM + fused LN/ReLU ----------------
#define SBK 64
#define SAGE2_SMEM (SBK * HD * 4 + 128 * SBK * 4)   // 65536

__global__ __launch_bounds__(256, 2)
void sage2_kernel(const float* __restrict__ hin,
                  const float* __restrict__ wT,
                  const float* __restrict__ bl,
                  const float* __restrict__ gg,
                  const float* __restrict__ be,
                  float* __restrict__ hout) {
    extern __shared__ float sm[];
    float* w_s = sm;                 // [64][128]
    float* x_s = sm + SBK * HD;      // [128][64]

    int tid = threadIdx.x;
    int tx = tid & 31;
    int wy = tid >> 5;
    int row0 = blockIdx.x * 128;

    float acc[16][4];
#pragma unroll
    for (int r = 0; r < 16; r++) {
        acc[r][0] = 0.f; acc[r][1] = 0.f; acc[r][2] = 0.f; acc[r][3] = 0.f;
    }

    for (int ch = 0; ch < 4; ch++) {
        const float* xsrc = (ch < 2) ? g_agg : hin;
        int kofs = (ch & 1) * SBK;
        {
            int k4 = tid & 15, rr = tid >> 4;
#pragma unroll
            for (int it = 0; it < 8; it++) {
                int row = rr + it * 16;
                int grow = row0 + row;
                float4 v = make_float4(0.f, 0.f, 0.f, 0.f);
                if (grow < NN)
                    v = *(const float4*)(xsrc + (size_t)grow * HD + kofs + k4 * 4);
                ((float4*)(x_s + row * SBK))[k4] = v;
            }
        }
        {
            int c4 = tid & 31, kk = tid >> 5;
#pragma unroll
            for (int it = 0; it < 8; it++) {
                int k = kk + it * 8;
                ((float4*)(w_s + k * HD))[c4] =
                    *(const float4*)(wT + (size_t)(ch * SBK + k) * HD + c4 * 4);
            }
        }
        __syncthreads();

#pragma unroll 4
        for (int k4i = 0; k4i < SBK / 4; k4i++) {
            float4 b0 = ((float4*)(w_s + (4 * k4i + 0) * HD))[tx];
            float4 b1 = ((float4*)(w_s + (4 * k4i + 1) * HD))[tx];
            float4 b2 = ((float4*)(w_s + (4 * k4i + 2) * HD))[tx];
            float4 b3 = ((float4*)(w_s + (4 * k4i + 3) * HD))[tx];
#pragma unroll
            for (int r = 0; r < 16; r++) {
                float4 a = ((float4*)(x_s + (wy * 16 + r) * SBK))[k4i];  // broadcast
                acc[r][0] += a.x * b0.x + a.y * b1.x + a.z * b2.x + a.w * b3.x;
                acc[r][1] += a.x * b0.y + a.y * b1.y + a.z * b2.y + a.w * b3.y;
                acc[r][2] += a.x * b0.z + a.y * b1.z + a.z * b2.z + a.w * b3.z;
                acc[r][3] += a.x * b0.w + a.y * b1.w + a.z * b2.w + a.w * b3.w;
            }
        }
        __syncthreads();
    }

    float4 blv = *(const float4*)(bl + tx * 4);
    float4 gv  = *(const float4*)(gg + tx * 4);
    float4 bev = *(const float4*)(be + tx * 4);
#pragma unroll
    for (int r = 0; r < 16; r++) {
        float a0 = acc[r][0] + blv.x;
        float a1 = acc[r][1] + blv.y;
        float a2 = acc[r][2] + blv.z;
        float a3 = acc[r][3] + blv.w;
        float s1 = (a0 + a1) + (a2 + a3);
        float s2 = (a0 * a0 + a1 * a1) + (a2 * a2 + a3 * a3);
#pragma unroll
        for (int o = 16; o; o >>= 1) {
            s1 += __shfl_xor_sync(0xffffffffu, s1, o);
            s2 += __shfl_xor_sync(0xffffffffu, s2, o);
        }
        float mean = s1 * (1.0f / HD);
        float var  = s2 * (1.0f / HD) - mean * mean;
        float rs   = rsqrtf(var + LN_EPS);
        int row = row0 + wy * 16 + r;
        if (row < NN) {
            float4 o4;
            o4.x = fmaxf((a0 - mean) * rs * gv.x + bev.x, 0.f);
            o4.y = fmaxf((a1 - mean) * rs * gv.y + bev.y, 0.f);
            o4.z = fmaxf((a2 - mean) * rs * gv.z + bev.z, 0.f);
            o4.w = fmaxf((a3 - mean) * rs * gv.w + bev.w, 0.f);
            *(float4*)(hout + (size_t)row * HD + tx * 4) = o4;
        }
    }
}

// ---------------- pooling ----------------
#define POOL_CHUNK 256
__global__ void pool_kernel(const float* __restrict__ node,
                            const int* __restrict__ batch) {
    int n0 = blockIdx.x * POOL_CHUNK;
    int n1 = min(n0 + POOL_CHUNK, NN);
    int c = threadIdx.x;
    int cur = __ldg(&batch[n0]);
    float s = 0.0f, m = 0.0f;
    int cnt = 0;
    for (int i = n0; i < n1; i++) {
        int b = __ldg(&batch[i]);
        if (b != cur) {
            atomicAdd(&g_psum[cur * HD + c], s);
            atomicMax(&g_pmax[cur * HD + c], __float_as_uint(m));
            if (c == 0) atomicAdd(&g_pcnt[cur], cnt);
            cur = b; s = 0.0f; m = 0.0f; cnt = 0;
        }
        float v = node[(size_t)i * HD + c];
        s += v;
        m = fmaxf(m, v);
        cnt++;
    }
    atomicAdd(&g_psum[cur * HD + c], s);
    atomicMax(&g_pmax[cur * HD + c], __float_as_uint(m));
    if (c == 0) atomicAdd(&g_pcnt[cur], cnt);
}

__global__ void finalize_kernel(float* __restrict__ out) {
    int i = blockIdx.x * blockDim.x + threadIdx.x;
    if (i >= BB * HD) return;
    int b = i >> 7;
    int c = i & (HD - 1);
    float cnt = fmaxf((float)g_pcnt[b], 1.0f);
    out[(size_t)NN * HD + b * (2 * HD) + c] = g_psum[i] / cnt;
    out[(size_t)NN * HD + b * (2 * HD) + HD + c] = __uint_as_float(g_pmax[i]);
}

// ---------------- launch ----------------
extern "C" void kernel_launch(void* const* d_in, const int* in_sizes, int n_in,
                              void* d_out, int out_size) {
    const float* x   = (const float*)d_in[0];
    const int* eidx  = (const int*)d_in[1];
    const int* batch = (const int*)d_in[2];
    const float* W0 = (const float*)d_in[3];
    const float* b0 = (const float*)d_in[4];
    const float* g0 = (const float*)d_in[5];
    const float* be0 = (const float*)d_in[6];
    const float* Wl1 = (const float*)d_in[7];
    const float* bl1 = (const float*)d_in[8];
    const float* Wr1 = (const float*)d_in[9];
    const float* g1 = (const float*)d_in[10];
    const float* be1 = (const float*)d_in[11];
    const float* Wl2 = (const float*)d_in[12];
    const float* bl2 = (const float*)d_in[13];
    const float* Wr2 = (const float*)d_in[14];
    const float* g2 = (const float*)d_in[15];
    const float* be2 = (const float*)d_in[16];
    const float* Wl3 = (const float*)d_in[17];
    const float* bl3 = (const float*)d_in[18];
    const float* Wr3 = (const float*)d_in[19];
    const float* g3 = (const float*)d_in[20];
    const float* be3 = (const float*)d_in[21];
    float* out = (float*)d_out;

    const int* src = eidx;       // edge_index[0]
    const int* dst = eidx + EE;  // edge_index[1]

    static int attr_set = 0;
    if (!attr_set) {
        cudaFuncSetAttribute(sage2_kernel,
                             cudaFuncAttributeMaxDynamicSharedMemorySize, SAGE2_SMEM);
        attr_set = 1;
    }

    float* wT = 0;
    cudaGetSymbolAddress((void**)&wT, g_wT);

    int agg_blocks = (NN * 32 + 255) / 256;
    int sage_blocks = (NN + 127) / 128;

    // 1: init + weight transpose
    init_kernel<<<(NN + 255) / 256, 256>>>(Wl1, Wr1, Wl2, Wr2, Wl3, Wr3);
    // 2: bucket build
    build_kernel<<<(EE + 255) / 256, 256>>>(src, dst);
    // 3: embed
    embed_kernel<<<NN / ROWS_E, HD>>>(x, W0, b0, g0, be0, g_h0);
    // 4: aggregate (profiled slot)
    aggregate_kernel<<<agg_blocks, 256>>>(g_h0);
    sage2_kernel<<<sage_blocks, 256, SAGE2_SMEM>>>(g_h0, wT + 0 * KK * HD, bl1, g1, be1, g_h1);
    aggregate_kernel<<<agg_blocks, 256>>>(g_h1);
    sage2_kernel<<<sage_blocks, 256, SAGE2_SMEM>>>(g_h1, wT + 1 * KK * HD, bl2, g2, be2, g_h0);
    aggregate_kernel<<<agg_blocks, 256>>>(g_h0);
    sage2_kernel<<<sage_blocks, 256, SAGE2_SMEM>>>(g_h0, wT + 2 * KK * HD, bl3, g3, be3, out);

    // pooling
    pool_kernel<<<(NN + POOL_CHUNK - 1) / POOL_CHUNK, HD>>>(out, batch);
    finalize_kernel<<<(BB * HD + 255) / 256, 256>>>(out);
}

// round 11
// speedup vs baseline: 1.0131x; 1.0065x over previous
#include <cuda_runtime.h>
#include <math.h>

#define NN 100000
#define EE 1600000
#define BB 64
#define DIN 9
#define HD 128
#define KK 256
#define SLOTS 96
#define LN_EPS 1e-5f

// ---------------- scratch (zero at module load; cleanup restores zero each call) ----------------
__device__ float g_h0[NN * HD];
__device__ float g_h1[NN * HD];
__device__ float g_agg[NN * HD];
__device__ float g_wT[3 * KK * HD];   // per layer: [k][c]; k<128 = Wl^T, k>=128 = Wr^T
__device__ int   g_deg[NN];
__device__ int   g_slots[NN * SLOTS];
__device__ float g_psum[BB * HD];
__device__ unsigned g_pmax[BB * HD];
__device__ int   g_pcnt[BB];

// ---------------- launch 1: bucket build + weight transpose (fused) ----------------
__global__ void build_kernel(const int* __restrict__ src, const int* __restrict__ dst,
                             const float* __restrict__ Wl1, const float* __restrict__ Wr1,
                             const float* __restrict__ Wl2, const float* __restrict__ Wr2,
                             const float* __restrict__ Wl3, const float* __restrict__ Wr3) {
    int e = blockIdx.x * blockDim.x + threadIdx.x;
    if (e < 3 * KK * HD) {
        int c = e & 127;
        int k = (e >> 7) & 255;
        int L = e >> 15;
        const float* W;
        int kk = k;
        if (k < HD) {
            W = (L == 0) ? Wl1 : (L == 1) ? Wl2 : Wl3;
        } else {
            W = (L == 0) ? Wr1 : (L == 1) ? Wr2 : Wr3;
            kk = k - HD;
        }
        g_wT[e] = W[c * HD + kk];
    }
    if (e < EE) {
        int d = dst[e];
        int pos = atomicAdd(&g_deg[d], 1);
        if (pos < SLOTS) g_slots[d * SLOTS + pos] = src[e];
    }
}

// ---------------- launch 2: node embedder Linear(9->128) + LN + ReLU ----------------
#define ROWS_E 16
__global__ void embed_kernel(const float* __restrict__ x,
                             const float* __restrict__ W0,
                             const float* __restrict__ b0,
                             const float* __restrict__ g0,
                             const float* __restrict__ be0,
                             float* __restrict__ hout) {
    __shared__ float sx[DIN];
    __shared__ float red[8];
    int tid = threadIdx.x;
    float gc = g0[tid], bec = be0[tid], bc = b0[tid];
    float w[DIN];
#pragma unroll
    for (int k = 0; k < DIN; k++) w[k] = W0[tid * DIN + k];

    int row0 = blockIdx.x * ROWS_E;
    for (int r = 0; r < ROWS_E; r++) {
        int row = row0 + r;
        if (tid < DIN) sx[tid] = x[row * DIN + tid];
        __syncthreads();
        float acc = bc;
#pragma unroll
        for (int k = 0; k < DIN; k++) acc += w[k] * sx[k];
        float s1 = acc, s2 = acc * acc;
#pragma unroll
        for (int o = 16; o; o >>= 1) {
            s1 += __shfl_xor_sync(0xffffffffu, s1, o);
            s2 += __shfl_xor_sync(0xffffffffu, s2, o);
        }
        int wi = tid >> 5, l = tid & 31;
        if (l == 0) { red[wi] = s1; red[wi + 4] = s2; }
        __syncthreads();
        float t1 = red[0] + red[1] + red[2] + red[3];
        float t2 = red[4] + red[5] + red[6] + red[7];
        float mean = t1 * (1.0f / HD);
        float var = t2 * (1.0f / HD) - mean * mean;
        float rs = rsqrtf(var + LN_EPS);
        float v = (acc - mean) * rs * gc + bec;
        hout[row * HD + tid] = fmaxf(v, 0.0f);
        __syncthreads();
    }
}

// ---------------- mean aggregation: warp per node, broadcast index loads, MLP=8 ----------------
__global__ void aggregate_kernel(const float* __restrict__ hin) {
    int node = (blockIdx.x * blockDim.x + threadIdx.x) >> 5;
    int lane = threadIdx.x & 31;
    if (node >= NN) return;
    int deg = g_deg[node];
    int n = min(deg, SLOTS);
    const int* sl = g_slots + node * SLOTS;

    float a0 = 0.f, a1 = 0.f, a2 = 0.f, a3 = 0.f;
    int j = 0;
    for (; j + 8 <= n; j += 8) {
        int i0 = sl[j + 0], i1 = sl[j + 1], i2 = sl[j + 2], i3 = sl[j + 3];
        int i4 = sl[j + 4], i5 = sl[j + 5], i6 = sl[j + 6], i7 = sl[j + 7];
        float4 v0 = *((const float4*)(hin + (size_t)i0 * HD) + lane);
        float4 v1 = *((const float4*)(hin + (size_t)i1 * HD) + lane);
        float4 v2 = *((const float4*)(hin + (size_t)i2 * HD) + lane);
        float4 v3 = *((const float4*)(hin + (size_t)i3 * HD) + lane);
        float4 v4 = *((const float4*)(hin + (size_t)i4 * HD) + lane);
        float4 v5 = *((const float4*)(hin + (size_t)i5 * HD) + lane);
        float4 v6 = *((const float4*)(hin + (size_t)i6 * HD) + lane);
        float4 v7 = *((const float4*)(hin + (size_t)i7 * HD) + lane);
        a0 += ((v0.x + v1.x) + (v2.x + v3.x)) + ((v4.x + v5.x) + (v6.x + v7.x));
        a1 += ((v0.y + v1.y) + (v2.y + v3.y)) + ((v4.y + v5.y) + (v6.y + v7.y));
        a2 += ((v0.z + v1.z) + (v2.z + v3.z)) + ((v4.z + v5.z) + (v6.z + v7.z));
        a3 += ((v0.w + v1.w) + (v2.w + v3.w)) + ((v4.w + v5.w) + (v6.w + v7.w));
    }
    for (; j + 2 <= n; j += 2) {
        int i0 = sl[j + 0], i1 = sl[j + 1];
        float4 v0 = *((const float4*)(hin + (size_t)i0 * HD) + lane);
        float4 v1 = *((const float4*)(hin + (size_t)i1 * HD) + lane);
        a0 += v0.x + v1.x; a1 += v0.y + v1.y;
        a2 += v0.z + v1.z; a3 += v0.w + v1.w;
    }
    if (j < n) {
        int i0 = sl[j];
        float4 v = *((const float4*)(hin + (size_t)i0 * HD) + lane);
        a0 += v.x; a1 += v.y; a2 += v.z; a3 += v.w;
    }
    float inv = 1.0f / (float)max(deg, 1);
    float4 out;
    out.x = a0 * inv; out.y = a1 * inv; out.z = a2 * inv; out.w = a3 * inv;
    *reinterpret_cast<float4*>(g_agg + (size_t)node * HD + lane * 4) = out;
}

// ---------------- SAGE v3: 64x128xK=256 register-tiled GEMM + fused LN/ReLU ----------------
// 256 threads: tx=tid&31 -> channels tx*4..+3; wy=tid>>5 (8 warps) -> rows wy*8..+7.
// Thread tile 8 rows x 4 ch = 32 accumulators (~70 regs, NO spill at 85-reg budget).
// smem: w_s[64][128] (32KB) + x_s[64][64] (16KB) = 48KB -> 3 CTAs/SM.
#define SBK 64
#define SROWS 64
#define SAGE3_SMEM (SBK * HD * 4 + SROWS * SBK * 4)   // 49152

__global__ __launch_bounds__(256, 3)
void sage3_kernel(const float* __restrict__ hin,
                  const float* __restrict__ wT,
                  const float* __restrict__ bl,
                  const float* __restrict__ gg,
                  const float* __restrict__ be,
                  float* __restrict__ hout) {
    extern __shared__ float sm[];
    float* w_s = sm;                 // [64][128]
    float* x_s = sm + SBK * HD;      // [64][64]

    int tid = threadIdx.x;
    int tx = tid & 31;
    int wy = tid >> 5;
    int row0 = blockIdx.x * SROWS;

    float acc[8][4];
#pragma unroll
    for (int r = 0; r < 8; r++) {
        acc[r][0] = 0.f; acc[r][1] = 0.f; acc[r][2] = 0.f; acc[r][3] = 0.f;
    }

    for (int ch = 0; ch < 4; ch++) {
        const float* xsrc = (ch < 2) ? g_agg : hin;
        int kofs = (ch & 1) * SBK;
        // stage x: 64 rows x 64 k (coalesced LDG, conflict-free STS.128)
        {
            int k4 = tid & 15, rr = tid >> 4;
#pragma unroll
            for (int it = 0; it < 4; it++) {
                int row = rr + it * 16;
                int grow = row0 + row;
                float4 v = make_float4(0.f, 0.f, 0.f, 0.f);
                if (grow < NN)
                    v = *(const float4*)(xsrc + (size_t)grow * HD + kofs + k4 * 4);
                ((float4*)(x_s + row * SBK))[k4] = v;
            }
        }
        // stage w: 64 k x 128 c from pre-transposed wT
        {
            int c4 = tid & 31, kk = tid >> 5;
#pragma unroll
            for (int it = 0; it < 8; it++) {
                int k = kk + it * 8;
                ((float4*)(w_s + k * HD))[c4] =
                    *(const float4*)(wT + (size_t)(ch * SBK + k) * HD + c4 * 4);
            }
        }
        __syncthreads();

#pragma unroll 4
        for (int k4i = 0; k4i < SBK / 4; k4i++) {
            float4 b0 = ((float4*)(w_s + (4 * k4i + 0) * HD))[tx];
            float4 b1 = ((float4*)(w_s + (4 * k4i + 1) * HD))[tx];
            float4 b2 = ((float4*)(w_s + (4 * k4i + 2) * HD))[tx];
            float4 b3 = ((float4*)(w_s + (4 * k4i + 3) * HD))[tx];
#pragma unroll
            for (int r = 0; r < 8; r++) {
                float4 a = ((float4*)(x_s + (wy * 8 + r) * SBK))[k4i];  // broadcast
                acc[r][0] += a.x * b0.x + a.y * b1.x + a.z * b2.x + a.w * b3.x;
                acc[r][1] += a.x * b0.y + a.y * b1.y + a.z * b2.y + a.w * b3.y;
                acc[r][2] += a.x * b0.z + a.y * b1.z + a.z * b2.z + a.w * b3.z;
                acc[r][3] += a.x * b0.w + a.y * b1.w + a.z * b2.w + a.w * b3.w;
            }
        }
        __syncthreads();
    }

    // epilogue: bias + LayerNorm (full 128-ch reduction within warp) + ReLU
    float4 blv = *(const float4*)(bl + tx * 4);
    float4 gv  = *(const float4*)(gg + tx * 4);
    float4 bev = *(const float4*)(be + tx * 4);
#pragma unroll
    for (int r = 0; r < 8; r++) {
        float a0 = acc[r][0] + blv.x;
        float a1 = acc[r][1] + blv.y;
        float a2 = acc[r][2] + blv.z;
        float a3 = acc[r][3] + blv.w;
        float s1 = (a0 + a1) + (a2 + a3);
        float s2 = (a0 * a0 + a1 * a1) + (a2 * a2 + a3 * a3);
#pragma unroll
        for (int o = 16; o; o >>= 1) {
            s1 += __shfl_xor_sync(0xffffffffu, s1, o);
            s2 += __shfl_xor_sync(0xffffffffu, s2, o);
        }
        float mean = s1 * (1.0f / HD);
        float var  = s2 * (1.0f / HD) - mean * mean;
        float rs   = rsqrtf(var + LN_EPS);
        int row = row0 + wy * 8 + r;
        if (row < NN) {
            float4 o4;
            o4.x = fmaxf((a0 - mean) * rs * gv.x + bev.x, 0.f);
            o4.y = fmaxf((a1 - mean) * rs * gv.y + bev.y, 0.f);
            o4.z = fmaxf((a2 - mean) * rs * gv.z + bev.z, 0.f);
            o4.w = fmaxf((a3 - mean) * rs * gv.w + bev.w, 0.f);
            *(float4*)(hout + (size_t)row * HD + tx * 4) = o4;
        }
    }
}

// ---------------- pooling ----------------
#define POOL_CHUNK 256
__global__ void pool_kernel(const float* __restrict__ node,
                            const int* __restrict__ batch) {
    int n0 = blockIdx.x * POOL_CHUNK;
    int n1 = min(n0 + POOL_CHUNK, NN);
    int c = threadIdx.x;
    int cur = __ldg(&batch[n0]);
    float s = 0.0f, m = 0.0f;
    int cnt = 0;
    for (int i = n0; i < n1; i++) {
        int b = __ldg(&batch[i]);
        if (b != cur) {
            atomicAdd(&g_psum[cur * HD + c], s);
            atomicMax(&g_pmax[cur * HD + c], __float_as_uint(m));
            if (c == 0) atomicAdd(&g_pcnt[cur], cnt);
            cur = b; s = 0.0f; m = 0.0f; cnt = 0;
        }
        float v = node[(size_t)i * HD + c];
        s += v;
        m = fmaxf(m, v);
        cnt++;
    }
    atomicAdd(&g_psum[cur * HD + c], s);
    atomicMax(&g_pmax[cur * HD + c], __float_as_uint(m));
    if (c == 0) atomicAdd(&g_pcnt[cur], cnt);
}

__global__ void finalize_kernel(float* __restrict__ out) {
    int i = blockIdx.x * blockDim.x + threadIdx.x;
    if (i >= BB * HD) return;
    int b = i >> 7;
    int c = i & (HD - 1);
    float cnt = fmaxf((float)g_pcnt[b], 1.0f);
    out[(size_t)NN * HD + b * (2 * HD) + c] = g_psum[i] / cnt;
    out[(size_t)NN * HD + b * (2 * HD) + HD + c] = __uint_as_float(g_pmax[i]);
}

// ---------------- cleanup: restore zero state for next call (graph-replay safe) ----------------
__global__ void cleanup_kernel() {
    int i = blockIdx.x * blockDim.x + threadIdx.x;
    if (i < NN) g_deg[i] = 0;
    if (i < BB * HD) { g_psum[i] = 0.0f; g_pmax[i] = 0u; }
    if (i < BB) g_pcnt[i] = 0;
}

// ---------------- launch ----------------
extern "C" void kernel_launch(void* const* d_in, const int* in_sizes, int n_in,
                              void* d_out, int out_size) {
    const float* x   = (const float*)d_in[0];
    const int* eidx  = (const int*)d_in[1];
    const int* batch = (const int*)d_in[2];
    const float* W0 = (const float*)d_in[3];
    const float* b0 = (const float*)d_in[4];
    const float* g0 = (const float*)d_in[5];
    const float* be0 = (const float*)d_in[6];
    const float* Wl1 = (const float*)d_in[7];
    const float* bl1 = (const float*)d_in[8];
    const float* Wr1 = (const float*)d_in[9];
    const float* g1 = (const float*)d_in[10];
    const float* be1 = (const float*)d_in[11];
    const float* Wl2 = (const float*)d_in[12];
    const float* bl2 = (const float*)d_in[13];
    const float* Wr2 = (const float*)d_in[14];
    const float* g2 = (const float*)d_in[15];
    const float* be2 = (const float*)d_in[16];
    const float* Wl3 = (const float*)d_in[17];
    const float* bl3 = (const float*)d_in[18];
    const float* Wr3 = (const float*)d_in[19];
    const float* g3 = (const float*)d_in[20];
    const float* be3 = (const float*)d_in[21];
    float* out = (float*)d_out;

    const int* src = eidx;       // edge_index[0]
    const int* dst = eidx + EE;  // edge_index[1]

    static int attr_set = 0;
    if (!attr_set) {
        cudaFuncSetAttribute(sage3_kernel,
                             cudaFuncAttributeMaxDynamicSharedMemorySize, SAGE3_SMEM);
        attr_set = 1;
    }

    float* wT = 0;
    cudaGetSymbolAddress((void**)&wT, g_wT);

    int agg_blocks = (NN * 32 + 255) / 256;
    int sage_blocks = (NN + SROWS - 1) / SROWS;

    // 1: bucket build + weight transpose (state is zero at entry)
    build_kernel<<<(EE + 255) / 256, 256>>>(src, dst, Wl1, Wr1, Wl2, Wr2, Wl3, Wr3);
    // 2: embed
    embed_kernel<<<NN / ROWS_E, HD>>>(x, W0, b0, g0, be0, g_h0);
    // 3: aggregate
    aggregate_kernel<<<agg_blocks, 256>>>(g_h0);
    // 4: sage layer 1 (PROFILED SLOT)
    sage3_kernel<<<sage_blocks, 256, SAGE3_SMEM>>>(g_h0, wT + 0 * KK * HD, bl1, g1, be1, g_h1);
    // layer 2
    aggregate_kernel<<<agg_blocks, 256>>>(g_h1);
    sage3_kernel<<<sage_blocks, 256, SAGE3_SMEM>>>(g_h1, wT + 1 * KK * HD, bl2, g2, be2, g_h0);
    // layer 3 -> out
    aggregate_kernel<<<agg_blocks, 256>>>(g_h0);
    sage3_kernel<<<sage_blocks, 256, SAGE3_SMEM>>>(g_h0, wT + 2 * KK * HD, bl3, g3, be3, out);

    // pooling
    pool_kernel<<<(NN + POOL_CHUNK - 1) / POOL_CHUNK, HD>>>(out, batch);
    finalize_kernel<<<(BB * HD + 255) / 256, 256>>>(out);

    // restore zero state for the next (graph-replayed) call
    cleanup_kernel<<<(NN + 255) / 256, 256>>>();
}